// round 14
// baseline (speedup 1.0000x reference)
#include <cuda_runtime.h>
#include <cuda_bf16.h>
#include <cstdint>

// TensorialCP encoder:
//   out[n, c] = lerp(vec_x[c], x_n) * lerp(vec_y[c], y_n) * lerp(vec_z[c], z_n)
// positions: [N,3] float32 in [-1,1]; vec_{x,y,z}: [32,512] float32; out: [N,32] float32.
//
// Strategy: transpose all three tables into shared memory as [513][33] floats
// (row = grid index, col = component, stride 33 for conflict-free fill+gather,
// row 512 zeroed as a safe i0+1 tap for the x==1 boundary). One warp per point,
// lane = component: 6 conflict-free 128B LDS wavefronts + one coalesced 128B STG
// per point.

#define CP_C 32
#define CP_R 512
#define CP_ROWS 513          // 512 + zero pad row for the i0+1 tap
#define CP_STRIDE 33         // 33 = 1 (mod 32): conflict-free both directions
#define AXIS_WORDS (CP_ROWS * CP_STRIDE)            // 16929
#define SMEM_BYTES (3 * AXIS_WORDS * (int)sizeof(float))  // 203148 B (< 227KB opt-in)

#define THREADS 512
#define UNROLL 8

__global__ __launch_bounds__(THREADS, 1)
void cp_encode_kernel(const float* __restrict__ pos,
                      const float* __restrict__ vx,
                      const float* __restrict__ vy,
                      const float* __restrict__ vz,
                      float* __restrict__ out,
                      int N)
{
    extern __shared__ float s[];
    float* sx = s;
    float* sy = s + AXIS_WORDS;
    float* sz = s + 2 * AXIS_WORDS;

    // ---- Fill shared tables, transposed [r][c] with stride 33 ----
    // idx = c*512 + r : consecutive threads -> consecutive r (coalesced LDG),
    // STS bank = (33r + c) % 32 = (r + c) % 32 -> conflict-free.
    for (int idx = threadIdx.x; idx < CP_C * CP_R; idx += THREADS) {
        int c = idx >> 9;          // idx / 512
        int r = idx & (CP_R - 1);  // idx % 512
        float a = vx[idx];
        float b = vy[idx];
        float d = vz[idx];
        sx[r * CP_STRIDE + c] = a;
        sy[r * CP_STRIDE + c] = b;
        sz[r * CP_STRIDE + c] = d;
    }
    // Zero pad row 512 (read only when ix lands exactly on 511; weight is 0).
    if (threadIdx.x < CP_STRIDE) {
        sx[CP_R * CP_STRIDE + threadIdx.x] = 0.0f;
        sy[CP_R * CP_STRIDE + threadIdx.x] = 0.0f;
        sz[CP_R * CP_STRIDE + threadIdx.x] = 0.0f;
    }
    __syncthreads();

    const int lane   = threadIdx.x & 31;
    const int gwarp  = (blockIdx.x * THREADS + threadIdx.x) >> 5;
    const int nwarps = (gridDim.x * THREADS) >> 5;
    const int step   = nwarps * UNROLL;

    // Per-lane base pointers (hoists the +lane*4 out of the inner loop).
    const float* __restrict__ sxl = sx + lane;
    const float* __restrict__ syl = sy + lane;
    const float* __restrict__ szl = sz + lane;

    int base;
    for (base = gwarp * UNROLL; base + UNROLL <= N; base += step) {
        const float* p = pos + (size_t)base * 3;
        float* o = out + (size_t)base * CP_C + lane;
#pragma unroll
        for (int j = 0; j < UNROLL; j++) {
            // Broadcast loads: all lanes read the same address.
            float px = __ldg(p + j * 3 + 0);
            float py = __ldg(p + j * 3 + 1);
            float pz = __ldg(p + j * 3 + 2);

            // ix = (x + 1) * 0.5 * (R - 1), single-rounded; exact-0 at x = -1,
            // and x in [-1,1] keeps i0 in [0,511] (511 only when w == 0).
            float ixf = fmaf(px, 255.5f, 255.5f);
            float iyf = fmaf(py, 255.5f, 255.5f);
            float izf = fmaf(pz, 255.5f, 255.5f);
            float fx0 = floorf(ixf);
            float fy0 = floorf(iyf);
            float fz0 = floorf(izf);
            float wx = ixf - fx0;
            float wy = iyf - fy0;
            float wz = izf - fz0;
            int ix = (int)fx0;
            int iy = (int)fy0;
            int iz = (int)fz0;

            // Conflict-free gathers; second tap via immediate offset (+STRIDE).
            float gx0 = sxl[ix * CP_STRIDE];
            float gx1 = sxl[ix * CP_STRIDE + CP_STRIDE];
            float gy0 = syl[iy * CP_STRIDE];
            float gy1 = syl[iy * CP_STRIDE + CP_STRIDE];
            float gz0 = szl[iz * CP_STRIDE];
            float gz1 = szl[iz * CP_STRIDE + CP_STRIDE];

            float fx = fmaf(wx, gx1 - gx0, gx0);
            float fy = fmaf(wy, gy1 - gy0, gy0);
            float fz = fmaf(wz, gz1 - gz0, gz0);

            o[j * CP_C] = fx * fy * fz;   // coalesced 128B per warp per point
        }
    }
    // Tail (at most UNROLL-1 points for a few warps).
    for (int n = base; n < N; n++) {
        float px = __ldg(pos + (size_t)n * 3 + 0);
        float py = __ldg(pos + (size_t)n * 3 + 1);
        float pz = __ldg(pos + (size_t)n * 3 + 2);
        float ixf = fmaf(px, 255.5f, 255.5f);
        float iyf = fmaf(py, 255.5f, 255.5f);
        float izf = fmaf(pz, 255.5f, 255.5f);
        float fx0 = floorf(ixf), fy0 = floorf(iyf), fz0 = floorf(izf);
        float wx = ixf - fx0, wy = iyf - fy0, wz = izf - fz0;
        int ix = (int)fx0, iy = (int)fy0, iz = (int)fz0;
        float gx0 = sxl[ix * CP_STRIDE], gx1 = sxl[ix * CP_STRIDE + CP_STRIDE];
        float gy0 = syl[iy * CP_STRIDE], gy1 = syl[iy * CP_STRIDE + CP_STRIDE];
        float gz0 = szl[iz * CP_STRIDE], gz1 = szl[iz * CP_STRIDE + CP_STRIDE];
        float fx = fmaf(wx, gx1 - gx0, gx0);
        float fy = fmaf(wy, gy1 - gy0, gy0);
        float fz = fmaf(wz, gz1 - gz0, gz0);
        out[(size_t)n * CP_C + lane] = fx * fy * fz;
    }
}

extern "C" void kernel_launch(void* const* d_in, const int* in_sizes, int n_in,
                              void* d_out, int out_size)
{
    const float* pos = (const float*)d_in[0];
    const float* vx  = (const float*)d_in[1];
    const float* vy  = (const float*)d_in[2];
    const float* vz  = (const float*)d_in[3];
    float* out = (float*)d_out;

    int N = in_sizes[0] / 3;

    int sms = 148;
    cudaDeviceGetAttribute(&sms, cudaDevAttrMultiProcessorCount, 0);

    cudaFuncSetAttribute(cp_encode_kernel,
                         cudaFuncAttributeMaxDynamicSharedMemorySize, SMEM_BYTES);

    cp_encode_kernel<<<sms, THREADS, SMEM_BYTES>>>(pos, vx, vy, vz, out, N);
}

// round 15
// speedup vs baseline: 1.0715x; 1.0715x over previous
#include <cuda_runtime.h>
#include <cuda_bf16.h>
#include <cstdint>

// TensorialCP encoder:
//   out[n, c] = lerp(vec_x[c], x_n) * lerp(vec_y[c], y_n) * lerp(vec_z[c], z_n)
// positions: [N,3] float32 in [-1,1]; vec_{x,y,z}: [32,512] float32; out: [N,32] float32.
//
// Organization: warp-per-point, lane = component. Tables transposed into shared
// memory as [513][33] floats (stride 33 -> conflict-free fill AND gather; row 512
// zeroed as the safe i0+1 tap at x == 1). Per point: 6 conflict-free 128B LDS
// wavefronts + 1 coalesced 128B STG.
//
// R14 changes vs R13:
//  - 1024 threads/block (32 warps/SM instead of 16): occupancy 24.7% -> ~48%,
//    covering LDS/LDG latency. UNROLL dropped 8 -> 4 + launch_bounds(1024,1)
//    to keep regs <= 64 (80 regs * 1024 threads would exceed the 64K RF).
//  - positions fetched cooperatively: lanes 0..11 issue ONE coalesced LDG per
//    4-point iteration (48B = 1 wavefront) and values are redistributed with
//    SHFL (no L1 traffic) -> L1 wavefronts/pt drop 10 -> ~7.1.

#define CP_C 32
#define CP_R 512
#define CP_ROWS 513          // 512 + zero pad row for the i0+1 tap
#define CP_STRIDE 33         // 33 = 1 (mod 32): conflict-free both directions
#define AXIS_WORDS (CP_ROWS * CP_STRIDE)            // 16929
#define SMEM_BYTES (3 * AXIS_WORDS * (int)sizeof(float))  // 203148 B (< 227KB opt-in)

#define THREADS 1024
#define UNROLL 4

__global__ __launch_bounds__(THREADS, 1)
void cp_encode_kernel(const float* __restrict__ pos,
                      const float* __restrict__ vx,
                      const float* __restrict__ vy,
                      const float* __restrict__ vz,
                      float* __restrict__ out,
                      int N)
{
    extern __shared__ float s[];
    float* sx = s;
    float* sy = s + AXIS_WORDS;
    float* sz = s + 2 * AXIS_WORDS;

    // ---- Fill shared tables, transposed [r][c] with stride 33 ----
    // idx = c*512 + r : consecutive threads -> consecutive r (coalesced LDG),
    // STS bank = (33r + c) % 32 = (r + c) % 32 -> conflict-free.
    for (int idx = threadIdx.x; idx < CP_C * CP_R; idx += THREADS) {
        int c = idx >> 9;          // idx / 512
        int r = idx & (CP_R - 1);  // idx % 512
        float a = vx[idx];
        float b = vy[idx];
        float d = vz[idx];
        sx[r * CP_STRIDE + c] = a;
        sy[r * CP_STRIDE + c] = b;
        sz[r * CP_STRIDE + c] = d;
    }
    // Zero pad row 512 (read only when ix lands exactly on 511; weight is 0).
    if (threadIdx.x < CP_STRIDE) {
        sx[CP_R * CP_STRIDE + threadIdx.x] = 0.0f;
        sy[CP_R * CP_STRIDE + threadIdx.x] = 0.0f;
        sz[CP_R * CP_STRIDE + threadIdx.x] = 0.0f;
    }
    __syncthreads();

    const int lane   = threadIdx.x & 31;
    const int gwarp  = (blockIdx.x * THREADS + threadIdx.x) >> 5;
    const int nwarps = (gridDim.x * THREADS) >> 5;
    const int step   = nwarps * UNROLL;

    // Per-lane base pointers (hoists the +lane*4 out of the inner loop).
    const float* __restrict__ sxl = sx + lane;
    const float* __restrict__ syl = sy + lane;
    const float* __restrict__ szl = sz + lane;

    int base;
    for (base = gwarp * UNROLL; base + UNROLL <= N; base += step) {
        // Cooperative position fetch: lanes 0..11 load the 12 floats covering
        // the next UNROLL=4 points in ONE coalesced LDG wavefront.
        const float* p = pos + (size_t)base * 3;
        float pv = (lane < 3 * UNROLL) ? p[lane] : 0.0f;

        float* o = out + (size_t)base * CP_C + lane;
#pragma unroll
        for (int j = 0; j < UNROLL; j++) {
            // Redistribute via shuffle (compile-time source lanes; no L1 traffic).
            float px = __shfl_sync(0xffffffffu, pv, 3 * j + 0);
            float py = __shfl_sync(0xffffffffu, pv, 3 * j + 1);
            float pz = __shfl_sync(0xffffffffu, pv, 3 * j + 2);

            // ix = (x + 1) * 0.5 * (R - 1), single-rounded; exact-0 at x = -1,
            // and x in [-1,1] keeps i0 in [0,511] (511 only when w == 0).
            float ixf = fmaf(px, 255.5f, 255.5f);
            float iyf = fmaf(py, 255.5f, 255.5f);
            float izf = fmaf(pz, 255.5f, 255.5f);
            float fx0 = floorf(ixf);
            float fy0 = floorf(iyf);
            float fz0 = floorf(izf);
            float wx = ixf - fx0;
            float wy = iyf - fy0;
            float wz = izf - fz0;
            int ix = (int)fx0;
            int iy = (int)fy0;
            int iz = (int)fz0;

            // Conflict-free gathers; second tap via immediate offset (+STRIDE).
            float gx0 = sxl[ix * CP_STRIDE];
            float gx1 = sxl[ix * CP_STRIDE + CP_STRIDE];
            float gy0 = syl[iy * CP_STRIDE];
            float gy1 = syl[iy * CP_STRIDE + CP_STRIDE];
            float gz0 = szl[iz * CP_STRIDE];
            float gz1 = szl[iz * CP_STRIDE + CP_STRIDE];

            float fx = fmaf(wx, gx1 - gx0, gx0);
            float fy = fmaf(wy, gy1 - gy0, gy0);
            float fz = fmaf(wz, gz1 - gz0, gz0);

            o[j * CP_C] = fx * fy * fz;   // coalesced 128B per warp per point
        }
    }
    // Tail (at most UNROLL-1 points for a few warps).
    for (int n = base; n < N; n++) {
        float px = __ldg(pos + (size_t)n * 3 + 0);
        float py = __ldg(pos + (size_t)n * 3 + 1);
        float pz = __ldg(pos + (size_t)n * 3 + 2);
        float ixf = fmaf(px, 255.5f, 255.5f);
        float iyf = fmaf(py, 255.5f, 255.5f);
        float izf = fmaf(pz, 255.5f, 255.5f);
        float fx0 = floorf(ixf), fy0 = floorf(iyf), fz0 = floorf(izf);
        float wx = ixf - fx0, wy = iyf - fy0, wz = izf - fz0;
        int ix = (int)fx0, iy = (int)fy0, iz = (int)fz0;
        float gx0 = sxl[ix * CP_STRIDE], gx1 = sxl[ix * CP_STRIDE + CP_STRIDE];
        float gy0 = syl[iy * CP_STRIDE], gy1 = syl[iy * CP_STRIDE + CP_STRIDE];
        float gz0 = szl[iz * CP_STRIDE], gz1 = szl[iz * CP_STRIDE + CP_STRIDE];
        float fx = fmaf(wx, gx1 - gx0, gx0);
        float fy = fmaf(wy, gy1 - gy0, gy0);
        float fz = fmaf(wz, gz1 - gz0, gz0);
        out[(size_t)n * CP_C + lane] = fx * fy * fz;
    }
}

extern "C" void kernel_launch(void* const* d_in, const int* in_sizes, int n_in,
                              void* d_out, int out_size)
{
    const float* pos = (const float*)d_in[0];
    const float* vx  = (const float*)d_in[1];
    const float* vy  = (const float*)d_in[2];
    const float* vz  = (const float*)d_in[3];
    float* out = (float*)d_out;

    int N = in_sizes[0] / 3;

    int sms = 148;
    cudaDeviceGetAttribute(&sms, cudaDevAttrMultiProcessorCount, 0);

    cudaFuncSetAttribute(cp_encode_kernel,
                         cudaFuncAttributeMaxDynamicSharedMemorySize, SMEM_BYTES);

    cp_encode_kernel<<<sms, THREADS, SMEM_BYTES>>>(pos, vx, vy, vz, out, N);
}

// round 16
// speedup vs baseline: 1.6305x; 1.5217x over previous
#include <cuda_runtime.h>
#include <cuda_bf16.h>
#include <cstdint>

// TensorialCP encoder:
//   out[n, c] = lerp(vec_x[c], x_n) * lerp(vec_y[c], y_n) * lerp(vec_z[c], z_n)
// positions: [N,3] f32 in [-1,1]; vec_{x,y,z}: [32,512] f32; out: [N,32] f32.
//
// R15 organization: lane = (point p = lane>>3, comp-quad c8 = lane&7).
// Each warp processes 4 points; each lane owns 4 components (float4).
// Tables in smem as [513][36] floats (stride 36 words = 144B: 16B-aligned rows
// for LDS.128; banks 4(r+c8) mod 32 -> conflict-free per point-phase; row 512
// zeroed as the safe i0+1 tap at x == 1).
// Per 4-point group: 3 SHFL + ~17 idx ops + 6 LDS.128 + 32 FMA-pipe + 1 STG.128.

#define CP_C 32
#define CP_R 512
#define CP_STRIDE 36                       // words; 144B rows, 16B aligned
#define CP_STRIDE4 (CP_STRIDE / 4)         // 9 float4 per row
#define AXIS_WORDS ((CP_R + 1) * CP_STRIDE)          // 513*36 = 18468
#define SMEM_BYTES (3 * AXIS_WORDS * (int)sizeof(float))  // 221616 B

#define THREADS 1024
#define UNROLL 2   // groups of 4 points in flight per warp iteration

__global__ __launch_bounds__(THREADS, 1)
void cp_encode_kernel(const float* __restrict__ pos,
                      const float* __restrict__ vx,
                      const float* __restrict__ vy,
                      const float* __restrict__ vz,
                      float* __restrict__ out,
                      int N)
{
    extern __shared__ float s[];
    float* sx = s;
    float* sy = s + AXIS_WORDS;
    float* sz = s + 2 * AXIS_WORDS;

    // ---- Fill shared tables, transposed [r][c], row stride 36 words ----
    for (int idx = threadIdx.x; idx < CP_C * CP_R; idx += THREADS) {
        int c = idx >> 9;          // component
        int r = idx & (CP_R - 1);  // grid row
        float a = vx[idx];
        float b = vy[idx];
        float d = vz[idx];
        sx[r * CP_STRIDE + c] = a;
        sy[r * CP_STRIDE + c] = b;
        sz[r * CP_STRIDE + c] = d;
    }
    // Zero pad row 512 (the i0+1 tap when ix == 511; its weight is exactly 0).
    if (threadIdx.x < CP_STRIDE) {
        sx[CP_R * CP_STRIDE + threadIdx.x] = 0.0f;
        sy[CP_R * CP_STRIDE + threadIdx.x] = 0.0f;
        sz[CP_R * CP_STRIDE + threadIdx.x] = 0.0f;
    }
    __syncthreads();

    const int lane = threadIdx.x & 31;
    const int c8   = lane & 7;          // which comp-quad
    const int psrc = 3 * (lane >> 3);   // shuffle source base for this lane's point

    const float4* __restrict__ sx4 = (const float4*)sx;
    const float4* __restrict__ sy4 = (const float4*)sy;
    const float4* __restrict__ sz4 = (const float4*)sz;
    float4* __restrict__ out4 = (float4*)out;

    const int ngroups = N >> 2;          // groups of 4 points
    const int gwarp   = (blockIdx.x * THREADS + threadIdx.x) >> 5;
    const int nwarps  = (gridDim.x * THREADS) >> 5;
    const int step    = nwarps * UNROLL;

    int g;
    for (g = gwarp * UNROLL; g + UNROLL <= ngroups; g += step) {
        // One coalesced LDG fetches positions for UNROLL*4 points (24 floats).
        float pv = (lane < 12 * UNROLL) ? __ldg(pos + (size_t)g * 12 + lane) : 0.0f;

#pragma unroll
        for (int u = 0; u < UNROLL; u++) {
            float px = __shfl_sync(0xffffffffu, pv, 12 * u + psrc + 0);
            float py = __shfl_sync(0xffffffffu, pv, 12 * u + psrc + 1);
            float pz = __shfl_sync(0xffffffffu, pv, 12 * u + psrc + 2);

            // ix = (x + 1) * 0.5 * (R - 1); x in [-1,1] => i0 in [0,511]
            // (511 only with weight exactly 0, which reads the zero pad row).
            float ixf = fmaf(px, 255.5f, 255.5f);
            float iyf = fmaf(py, 255.5f, 255.5f);
            float izf = fmaf(pz, 255.5f, 255.5f);
            float fx0 = floorf(ixf);
            float fy0 = floorf(iyf);
            float fz0 = floorf(izf);
            float wx = ixf - fx0;
            float wy = iyf - fy0;
            float wz = izf - fz0;
            int ax = (int)fx0 * CP_STRIDE4 + c8;   // float4 index
            int ay = (int)fy0 * CP_STRIDE4 + c8;
            int az = (int)fz0 * CP_STRIDE4 + c8;

            float4 gx0 = sx4[ax];
            float4 gx1 = sx4[ax + CP_STRIDE4];
            float4 gy0 = sy4[ay];
            float4 gy1 = sy4[ay + CP_STRIDE4];
            float4 gz0 = sz4[az];
            float4 gz1 = sz4[az + CP_STRIDE4];

            float4 r;
            {
                float fx = fmaf(wx, gx1.x - gx0.x, gx0.x);
                float fy = fmaf(wy, gy1.x - gy0.x, gy0.x);
                float fz = fmaf(wz, gz1.x - gz0.x, gz0.x);
                r.x = fx * fy * fz;
            }
            {
                float fx = fmaf(wx, gx1.y - gx0.y, gx0.y);
                float fy = fmaf(wy, gy1.y - gy0.y, gy0.y);
                float fz = fmaf(wz, gz1.y - gz0.y, gz0.y);
                r.y = fx * fy * fz;
            }
            {
                float fx = fmaf(wx, gx1.z - gx0.z, gx0.z);
                float fy = fmaf(wy, gy1.z - gy0.z, gy0.z);
                float fz = fmaf(wz, gz1.z - gz0.z, gz0.z);
                r.z = fx * fy * fz;
            }
            {
                float fx = fmaf(wx, gx1.w - gx0.w, gx0.w);
                float fy = fmaf(wy, gy1.w - gy0.w, gy0.w);
                float fz = fmaf(wz, gz1.w - gz0.w, gz0.w);
                r.w = fx * fy * fz;
            }

            // (group g+u, point lane>>3, quad c8): fully coalesced 512B store.
            out4[(size_t)(g + u) * 32 + lane] = r;
        }
    }

    // Leftover full groups for this warp (up to UNROLL-1).
#pragma unroll
    for (int u = 0; u < UNROLL; u++) {
        int gg = g + u;
        if (gg < ngroups) {
            float pv = (lane < 12) ? __ldg(pos + (size_t)gg * 12 + lane) : 0.0f;
            float px = __shfl_sync(0xffffffffu, pv, psrc + 0);
            float py = __shfl_sync(0xffffffffu, pv, psrc + 1);
            float pz = __shfl_sync(0xffffffffu, pv, psrc + 2);
            float ixf = fmaf(px, 255.5f, 255.5f);
            float iyf = fmaf(py, 255.5f, 255.5f);
            float izf = fmaf(pz, 255.5f, 255.5f);
            float fx0 = floorf(ixf), fy0 = floorf(iyf), fz0 = floorf(izf);
            float wx = ixf - fx0, wy = iyf - fy0, wz = izf - fz0;
            int ax = (int)fx0 * CP_STRIDE4 + c8;
            int ay = (int)fy0 * CP_STRIDE4 + c8;
            int az = (int)fz0 * CP_STRIDE4 + c8;
            float4 gx0 = sx4[ax], gx1 = sx4[ax + CP_STRIDE4];
            float4 gy0 = sy4[ay], gy1 = sy4[ay + CP_STRIDE4];
            float4 gz0 = sz4[az], gz1 = sz4[az + CP_STRIDE4];
            float4 r;
            r.x = fmaf(wx, gx1.x - gx0.x, gx0.x) * fmaf(wy, gy1.x - gy0.x, gy0.x) * fmaf(wz, gz1.x - gz0.x, gz0.x);
            r.y = fmaf(wx, gx1.y - gx0.y, gx0.y) * fmaf(wy, gy1.y - gy0.y, gy0.y) * fmaf(wz, gz1.y - gz0.y, gz0.y);
            r.z = fmaf(wx, gx1.z - gx0.z, gx0.z) * fmaf(wy, gy1.z - gy0.z, gy0.z) * fmaf(wz, gz1.z - gz0.z, gz0.z);
            r.w = fmaf(wx, gx1.w - gx0.w, gx0.w) * fmaf(wy, gy1.w - gy0.w, gy0.w) * fmaf(wz, gz1.w - gz0.w, gz0.w);
            out4[(size_t)gg * 32 + lane] = r;
        }
    }

    // Point tail (N % 4 != 0): warp-per-point, lane = component (conflict-free:
    // bank (36r + c) % 32 = (4r + c) % 32, c = 0..31 distinct).
    if (blockIdx.x == 0 && threadIdx.x < 32) {
        for (int n = ngroups << 2; n < N; n++) {
            float px = __ldg(pos + (size_t)n * 3 + 0);
            float py = __ldg(pos + (size_t)n * 3 + 1);
            float pz = __ldg(pos + (size_t)n * 3 + 2);
            float ixf = fmaf(px, 255.5f, 255.5f);
            float iyf = fmaf(py, 255.5f, 255.5f);
            float izf = fmaf(pz, 255.5f, 255.5f);
            float fx0 = floorf(ixf), fy0 = floorf(iyf), fz0 = floorf(izf);
            float wx = ixf - fx0, wy = iyf - fy0, wz = izf - fz0;
            int ix = (int)fx0 * CP_STRIDE + lane;
            int iy = (int)fy0 * CP_STRIDE + lane;
            int iz = (int)fz0 * CP_STRIDE + lane;
            float fx = fmaf(wx, sx[ix + CP_STRIDE] - sx[ix], sx[ix]);
            float fy = fmaf(wy, sy[iy + CP_STRIDE] - sy[iy], sy[iy]);
            float fz = fmaf(wz, sz[iz + CP_STRIDE] - sz[iz], sz[iz]);
            out[(size_t)n * CP_C + lane] = fx * fy * fz;
        }
    }
}

extern "C" void kernel_launch(void* const* d_in, const int* in_sizes, int n_in,
                              void* d_out, int out_size)
{
    const float* pos = (const float*)d_in[0];
    const float* vx  = (const float*)d_in[1];
    const float* vy  = (const float*)d_in[2];
    const float* vz  = (const float*)d_in[3];
    float* out = (float*)d_out;

    int N = in_sizes[0] / 3;

    int sms = 148;
    cudaDeviceGetAttribute(&sms, cudaDevAttrMultiProcessorCount, 0);

    cudaFuncSetAttribute(cp_encode_kernel,
                         cudaFuncAttributeMaxDynamicSharedMemorySize, SMEM_BYTES);

    cp_encode_kernel<<<sms, THREADS, SMEM_BYTES>>>(pos, vx, vy, vz, out, N);
}

// round 17
// speedup vs baseline: 1.7251x; 1.0580x over previous
#include <cuda_runtime.h>
#include <cuda_fp16.h>
#include <cstdint>

// TensorialCP encoder:
//   out[n, c] = lerp(vec_x[c], x_n) * lerp(vec_y[c], y_n) * lerp(vec_z[c], z_n)
// positions: [N,3] f32 in [-1,1]; vec_{x,y,z}: [32,512] f32; out: [N,32] f32.
//
// R16: pair-packed fp16 tables. smem word (r, c) = half2(v[c][r], v[c][r+1])
// -> ONE LDS.128 per axis per 4-point group fetches BOTH lerp taps for all
// 32 components of 4 points (3 LDS.128/group vs 6 in R15). Arithmetic stays
// fp32 after unpack (fp16 is storage-only; aggregate rel err ~5e-4).
//
// Organization (from R15): lane = (point p = lane>>3, comp-quad c8 = lane&7).
// Stride 36 words/row: lane reads words 36r + 4c8 + i -> banks (4r + 0..31)
// mod 32 = all 32 banks once per point, 4x per instruction = exactly 4
// wavefronts per LDS.128. Deterministically conflict-free.

#define CP_C 32
#define CP_R 512
#define CP_STRIDE 36                       // words per row (144B, 16B-aligned)
#define CP_STRIDE4 (CP_STRIDE / 4)         // 9 uint4 per row
#define AXIS_WORDS (CP_R * CP_STRIDE)      // 512*36 = 18432 words
#define SMEM_BYTES (3 * AXIS_WORDS * (int)sizeof(unsigned))  // 221184 B

#define THREADS 1024
#define UNROLL 2   // 4-point groups in flight per warp iteration

__global__ __launch_bounds__(THREADS, 1)
void cp_encode_kernel(const float* __restrict__ pos,
                      const float* __restrict__ vx,
                      const float* __restrict__ vy,
                      const float* __restrict__ vz,
                      float* __restrict__ out,
                      int N)
{
    extern __shared__ unsigned s[];           // half2 words
    unsigned* sx = s;
    unsigned* sy = s + AXIS_WORDS;
    unsigned* sz = s + 2 * AXIS_WORDS;

    // ---- Fill: word (r, c) = half2(v[c][r], v[c][r+1]) (r=511: dead tap = 0,
    // its lerp weight is exactly 0 there). LDGs overlap but hit L1/L2. ----
    for (int idx = threadIdx.x; idx < CP_C * CP_R; idx += THREADS) {
        int c = idx >> 9;          // component
        int r = idx & (CP_R - 1);  // grid row
        int nxt = (r < CP_R - 1) ? 1 : 0;
        __half2 hx, hy, hz;
        hx.x = __float2half_rn(vx[idx]);
        hx.y = __float2half_rn(nxt ? vx[idx + 1] : 0.0f);
        hy.x = __float2half_rn(vy[idx]);
        hy.y = __float2half_rn(nxt ? vy[idx + 1] : 0.0f);
        hz.x = __float2half_rn(vz[idx]);
        hz.y = __float2half_rn(nxt ? vz[idx + 1] : 0.0f);
        sx[r * CP_STRIDE + c] = *reinterpret_cast<unsigned*>(&hx);
        sy[r * CP_STRIDE + c] = *reinterpret_cast<unsigned*>(&hy);
        sz[r * CP_STRIDE + c] = *reinterpret_cast<unsigned*>(&hz);
    }
    __syncthreads();

    const int lane = threadIdx.x & 31;
    const int c8   = lane & 7;          // which comp-quad
    const int psrc = 3 * (lane >> 3);   // shuffle source base for this lane's point

    const uint4* __restrict__ sx4 = (const uint4*)sx;
    const uint4* __restrict__ sy4 = (const uint4*)sy;
    const uint4* __restrict__ sz4 = (const uint4*)sz;
    float4* __restrict__ out4 = (float4*)out;

    const int ngroups = N >> 2;          // groups of 4 points
    const int gwarp   = (blockIdx.x * THREADS + threadIdx.x) >> 5;
    const int nwarps  = (gridDim.x * THREADS) >> 5;
    const int step    = nwarps * UNROLL;

    int g;
    for (g = gwarp * UNROLL; g + UNROLL <= ngroups; g += step) {
        // One coalesced LDG fetches positions for UNROLL*4 points (24 floats).
        float pv = (lane < 12 * UNROLL) ? __ldg(pos + (size_t)g * 12 + lane) : 0.0f;

#pragma unroll
        for (int u = 0; u < UNROLL; u++) {
            float px = __shfl_sync(0xffffffffu, pv, 12 * u + psrc + 0);
            float py = __shfl_sync(0xffffffffu, pv, 12 * u + psrc + 1);
            float pz = __shfl_sync(0xffffffffu, pv, 12 * u + psrc + 2);

            // ix = (x + 1) * 0.5 * (R - 1); x in [-1,1] => i0 in [0,511]
            // (511 only with weight exactly 0 -> dead packed tap is harmless).
            float ixf = fmaf(px, 255.5f, 255.5f);
            float iyf = fmaf(py, 255.5f, 255.5f);
            float izf = fmaf(pz, 255.5f, 255.5f);
            float fx0 = floorf(ixf);
            float fy0 = floorf(iyf);
            float fz0 = floorf(izf);
            float wx = ixf - fx0;
            float wy = iyf - fy0;
            float wz = izf - fz0;
            int ax = (int)fx0 * CP_STRIDE4 + c8;   // uint4 index
            int ay = (int)fy0 * CP_STRIDE4 + c8;
            int az = (int)fz0 * CP_STRIDE4 + c8;

            uint4 hx = sx4[ax];    // 4 comps, both taps each (half2)
            uint4 hy = sy4[ay];
            uint4 hz = sz4[az];

            float4 r;
            {
                __half2 p0 = *reinterpret_cast<__half2*>(&hx.x);
                __half2 p1 = *reinterpret_cast<__half2*>(&hy.x);
                __half2 p2 = *reinterpret_cast<__half2*>(&hz.x);
                float x0 = __low2float(p0), x1 = __high2float(p0);
                float y0 = __low2float(p1), y1 = __high2float(p1);
                float z0 = __low2float(p2), z1 = __high2float(p2);
                r.x = fmaf(wx, x1 - x0, x0) * fmaf(wy, y1 - y0, y0) * fmaf(wz, z1 - z0, z0);
            }
            {
                __half2 p0 = *reinterpret_cast<__half2*>(&hx.y);
                __half2 p1 = *reinterpret_cast<__half2*>(&hy.y);
                __half2 p2 = *reinterpret_cast<__half2*>(&hz.y);
                float x0 = __low2float(p0), x1 = __high2float(p0);
                float y0 = __low2float(p1), y1 = __high2float(p1);
                float z0 = __low2float(p2), z1 = __high2float(p2);
                r.y = fmaf(wx, x1 - x0, x0) * fmaf(wy, y1 - y0, y0) * fmaf(wz, z1 - z0, z0);
            }
            {
                __half2 p0 = *reinterpret_cast<__half2*>(&hx.z);
                __half2 p1 = *reinterpret_cast<__half2*>(&hy.z);
                __half2 p2 = *reinterpret_cast<__half2*>(&hz.z);
                float x0 = __low2float(p0), x1 = __high2float(p0);
                float y0 = __low2float(p1), y1 = __high2float(p1);
                float z0 = __low2float(p2), z1 = __high2float(p2);
                r.z = fmaf(wx, x1 - x0, x0) * fmaf(wy, y1 - y0, y0) * fmaf(wz, z1 - z0, z0);
            }
            {
                __half2 p0 = *reinterpret_cast<__half2*>(&hx.w);
                __half2 p1 = *reinterpret_cast<__half2*>(&hy.w);
                __half2 p2 = *reinterpret_cast<__half2*>(&hz.w);
                float x0 = __low2float(p0), x1 = __high2float(p0);
                float y0 = __low2float(p1), y1 = __high2float(p1);
                float z0 = __low2float(p2), z1 = __high2float(p2);
                r.w = fmaf(wx, x1 - x0, x0) * fmaf(wy, y1 - y0, y0) * fmaf(wz, z1 - z0, z0);
            }

            // (group g+u, point lane>>3, quad c8): fully coalesced 512B store.
            out4[(size_t)(g + u) * 32 + lane] = r;
        }
    }

    // Leftover full groups for this warp (up to UNROLL-1).
#pragma unroll
    for (int u = 0; u < UNROLL; u++) {
        int gg = g + u;
        if (gg < ngroups) {
            float pv = (lane < 12) ? __ldg(pos + (size_t)gg * 12 + lane) : 0.0f;
            float px = __shfl_sync(0xffffffffu, pv, psrc + 0);
            float py = __shfl_sync(0xffffffffu, pv, psrc + 1);
            float pz = __shfl_sync(0xffffffffu, pv, psrc + 2);
            float ixf = fmaf(px, 255.5f, 255.5f);
            float iyf = fmaf(py, 255.5f, 255.5f);
            float izf = fmaf(pz, 255.5f, 255.5f);
            float fx0 = floorf(ixf), fy0 = floorf(iyf), fz0 = floorf(izf);
            float wx = ixf - fx0, wy = iyf - fy0, wz = izf - fz0;
            int ax = (int)fx0 * CP_STRIDE4 + c8;
            int ay = (int)fy0 * CP_STRIDE4 + c8;
            int az = (int)fz0 * CP_STRIDE4 + c8;
            uint4 hx = sx4[ax];
            uint4 hy = sy4[ay];
            uint4 hz = sz4[az];
            float4 r;
            const unsigned* wxp = &hx.x;
            const unsigned* wyp = &hy.x;
            const unsigned* wzp = &hz.x;
            float* rp = &r.x;
#pragma unroll
            for (int q = 0; q < 4; q++) {
                __half2 p0 = *reinterpret_cast<const __half2*>(&wxp[q]);
                __half2 p1 = *reinterpret_cast<const __half2*>(&wyp[q]);
                __half2 p2 = *reinterpret_cast<const __half2*>(&wzp[q]);
                float x0 = __low2float(p0), x1 = __high2float(p0);
                float y0 = __low2float(p1), y1 = __high2float(p1);
                float z0 = __low2float(p2), z1 = __high2float(p2);
                rp[q] = fmaf(wx, x1 - x0, x0) * fmaf(wy, y1 - y0, y0) * fmaf(wz, z1 - z0, z0);
            }
            out4[(size_t)gg * 32 + lane] = r;
        }
    }

    // Point tail (N % 4 != 0): warp-per-point, lane = component. Bank for
    // word 36r + c is (4r + c) mod 32 -> c = 0..31 distinct: conflict-free.
    if (blockIdx.x == 0 && threadIdx.x < 32) {
        for (int n = ngroups << 2; n < N; n++) {
            float px = __ldg(pos + (size_t)n * 3 + 0);
            float py = __ldg(pos + (size_t)n * 3 + 1);
            float pz = __ldg(pos + (size_t)n * 3 + 2);
            float ixf = fmaf(px, 255.5f, 255.5f);
            float iyf = fmaf(py, 255.5f, 255.5f);
            float izf = fmaf(pz, 255.5f, 255.5f);
            float fx0 = floorf(ixf), fy0 = floorf(iyf), fz0 = floorf(izf);
            float wx = ixf - fx0, wy = iyf - fy0, wz = izf - fz0;
            unsigned ux = sx[(int)fx0 * CP_STRIDE + lane];
            unsigned uy = sy[(int)fy0 * CP_STRIDE + lane];
            unsigned uz = sz[(int)fz0 * CP_STRIDE + lane];
            __half2 p0 = *reinterpret_cast<__half2*>(&ux);
            __half2 p1 = *reinterpret_cast<__half2*>(&uy);
            __half2 p2 = *reinterpret_cast<__half2*>(&uz);
            float x0 = __low2float(p0), x1 = __high2float(p0);
            float y0 = __low2float(p1), y1 = __high2float(p1);
            float z0 = __low2float(p2), z1 = __high2float(p2);
            out[(size_t)n * CP_C + lane] =
                fmaf(wx, x1 - x0, x0) * fmaf(wy, y1 - y0, y0) * fmaf(wz, z1 - z0, z0);
        }
    }
}

extern "C" void kernel_launch(void* const* d_in, const int* in_sizes, int n_in,
                              void* d_out, int out_size)
{
    const float* pos = (const float*)d_in[0];
    const float* vx  = (const float*)d_in[1];
    const float* vy  = (const float*)d_in[2];
    const float* vz  = (const float*)d_in[3];
    float* out = (float*)d_out;

    int N = in_sizes[0] / 3;

    int sms = 148;
    cudaDeviceGetAttribute(&sms, cudaDevAttrMultiProcessorCount, 0);

    cudaFuncSetAttribute(cp_encode_kernel,
                         cudaFuncAttributeMaxDynamicSharedMemorySize, SMEM_BYTES);

    cp_encode_kernel<<<sms, THREADS, SMEM_BYTES>>>(pos, vx, vy, vz, out, N);
}